// round 12
// baseline (speedup 1.0000x reference)
#include <cuda_runtime.h>
#include <cuda_fp16.h>
#include <math.h>
#include <stdint.h>

#define BB   64
#define TT   128
#define HH   50
#define VV   8192
#define G4H  200
#define PP   64
#define MM   4096

typedef __half h16;

// ---------------- helpers ----------------
__device__ __forceinline__ uint32_t smem_u32(const void* p) {
    uint32_t a;
    asm("{ .reg .u64 t; cvta.to.shared.u64 t, %1; cvt.u32.u64 %0, t; }" : "=r"(a) : "l"(p));
    return a;
}
__device__ __forceinline__ void cp16(uint32_t saddr, const void* gptr) {
    asm volatile("cp.async.cg.shared.global [%0], [%1], 16;" :: "r"(saddr), "l"(gptr));
}
__device__ __forceinline__ void ldsm4(uint32_t& r0, uint32_t& r1, uint32_t& r2, uint32_t& r3, uint32_t addr) {
    asm volatile("ldmatrix.sync.aligned.m8n8.x4.shared.b16 {%0,%1,%2,%3}, [%4];"
                 : "=r"(r0), "=r"(r1), "=r"(r2), "=r"(r3) : "r"(addr));
}
__device__ __forceinline__ void mma16816(float* c, const uint32_t* a, const uint32_t* b) {
    asm volatile("mma.sync.aligned.m16n8k16.row.col.f32.f16.f16.f32 "
                 "{%0,%1,%2,%3}, {%4,%5,%6,%7}, {%8,%9}, {%0,%1,%2,%3};"
                 : "+f"(c[0]), "+f"(c[1]), "+f"(c[2]), "+f"(c[3])
                 : "r"(a[0]), "r"(a[1]), "r"(a[2]), "r"(a[3]), "r"(b[0]), "r"(b[1]));
}
__device__ __forceinline__ float sigf(float x) { return 1.0f / (1.0f + expf(-x)); }

// ---------------- scratch globals ----------------
__device__ __align__(256) float g_Ewx[VV * G4H];
__device__ __align__(256) h16 g_pooled[MM * 64];
__device__ __align__(256) h16 g_W1t[VV * 64];
__device__ __align__(256) h16 g_W1bt[(size_t)VV * VV];
__device__ __align__(256) h16 g_W2t[(size_t)VV * VV];
__device__ __align__(256) h16 g_x1[(size_t)MM * VV];
__device__ __align__(256) h16 g_x2[(size_t)MM * VV];

// ---------------- kernel: Ewx = E@Wx + b (fp32) ----------------
__global__ void ewx_kernel(const float* __restrict__ E, const float* __restrict__ Wx,
                           const float* __restrict__ bias) {
    __shared__ float e[HH];
    int v = blockIdx.x;
    if (threadIdx.x < HH) e[threadIdx.x] = E[v * HH + threadIdx.x];
    __syncthreads();
    int k = threadIdx.x;
    if (k < G4H) {
        float acc = bias[k];
#pragma unroll
        for (int h = 0; h < HH; ++h) acc = fmaf(e[h], Wx[h * G4H + k], acc);
        g_Ewx[(size_t)v * G4H + k] = acc;
    }
}

// ---------------- kernel: W1 [50,V] -> W1t [V,64] fp16 (zero pad K) ----------------
__global__ void w1t_kernel(const float* __restrict__ W1) {
    int i = blockIdx.x * 256 + threadIdx.x;   // n*64 + k
    int n = i >> 6, k = i & 63;
    float v = (k < HH) ? W1[(size_t)k * VV + n] : 0.0f;
    g_W1t[i] = __float2half_rn(v);
}

// ---------------- kernel: transpose-convert W [K=V][N=V] fp32 -> Wt [N][K] fp16 ----------------
// 64x64 tiles, float4 loads, 8-byte (4 x fp16) stores -> 128B contiguous write segments.
__global__ void convT_kernel(const float* __restrict__ W, h16* __restrict__ Wt) {
    __shared__ float t[64][65];
    int tx = threadIdx.x, ty = threadIdx.y;   // 16 x 16
    int col = blockIdx.x * 64 + tx * 4;
#pragma unroll
    for (int i = 0; i < 4; ++i) {
        int row = blockIdx.y * 64 + ty + i * 16;
        float4 v = *(const float4*)&W[(size_t)row * VV + col];
        t[ty + i * 16][tx * 4 + 0] = v.x;
        t[ty + i * 16][tx * 4 + 1] = v.y;
        t[ty + i * 16][tx * 4 + 2] = v.z;
        t[ty + i * 16][tx * 4 + 3] = v.w;
    }
    __syncthreads();
#pragma unroll
    for (int i = 0; i < 4; ++i) {
        int n = blockIdx.x * 64 + ty + i * 16;
        int k = blockIdx.y * 64 + tx * 4;
        __half2 a = __floats2half2_rn(t[tx * 4 + 0][ty + i * 16], t[tx * 4 + 1][ty + i * 16]);
        __half2 b = __floats2half2_rn(t[tx * 4 + 2][ty + i * 16], t[tx * 4 + 3][ty + i * 16]);
        uint2 pack;
        pack.x = *(uint32_t*)&a;
        pack.y = *(uint32_t*)&b;
        *(uint2*)&Wt[(size_t)n * VV + k] = pack;
    }
}

// ---------------- LSTM scan + fused MaxPool(2), fp16 out ----------------
__global__ void lstm_kernel(const int* __restrict__ inp, const float* __restrict__ U,
                            const float* __restrict__ rec_mask) {
    __shared__ float sU[4 * HH * HH];
    __shared__ float rm[G4H], hm[G4H], z[G4H];
    __shared__ float h[HH], c[HH], hprev[HH];
    int b = blockIdx.x, tid = threadIdx.x;

    for (int i = tid; i < 4 * HH * HH; i += 256) sU[i] = U[i];
    if (tid < G4H) {
        int g = tid / HH, j = tid - g * HH;
        rm[tid] = rec_mask[((size_t)g * BB + b) * HH + j];
    }
    if (tid < HH) { h[tid] = 0.0f; c[tid] = 0.0f; hprev[tid] = 0.0f; }
    __syncthreads();

    for (int t = 0; t < TT; ++t) {
        if (tid < G4H) hm[tid] = h[tid % HH] * rm[tid];
        __syncthreads();
        if (tid < G4H) {
            int g = tid / HH, j = tid - g * HH;
            float acc = g_Ewx[(size_t)inp[b * TT + t] * G4H + tid];
            const float* Ug = sU + g * HH * HH + j;
            const float* hg = hm + g * HH;
#pragma unroll
            for (int k = 0; k < HH; ++k) acc = fmaf(hg[k], Ug[k * HH], acc);
            z[tid] = acc;
        }
        __syncthreads();
        if (tid < HH) {
            float iv = sigf(z[tid]);
            float fv = sigf(z[HH + tid]);
            float gv = tanhf(z[2 * HH + tid]);
            float ov = sigf(z[3 * HH + tid]);
            float cn = fv * c[tid] + iv * gv;
            float hn = ov * tanhf(cn);
            c[tid] = cn;
            h[tid] = hn;
            if (t & 1) {
                g_pooled[((size_t)b * PP + (t >> 1)) * 64 + tid] = __float2half_rn(fmaxf(hprev[tid], hn));
            } else hprev[tid] = hn;
        } else if (tid < 64 && (t & 1)) {
            g_pooled[((size_t)b * PP + (t >> 1)) * 64 + tid] = __float2half_rn(0.0f);
        }
        __syncthreads();
    }
}

// ---------------- fp16 HMMA GEMM (round-6 proven config, byte-identical mainloop) ----------------
// CTA 256x128xBK32, 512 threads (warp grid 4x4, tile 64x32), 4-stage cp.async ring, 120 KB smem.
// C[M=4096, N=8192] = epi(A[M,K] @ B[N,K]^T + bias)
// EPI 0: relu(+bias)*mask -> fp16.  EPI 1: sigmoid(+bias) -> fp32.
#define GBM 256
#define GBN 128
#define BKH 32
#define RSB 80                        // 64B data + 16B pad
#define A_BYTES (GBM * RSB)           // 20480
#define STAGE ((GBM + GBN) * RSB)     // 30720
#define GSMEM (4 * STAGE)             // 122880

template <int EPI>
__global__ void __launch_bounds__(512) hgemm(
    const h16* __restrict__ A, const h16* __restrict__ B, int K,
    const float* __restrict__ bias, const float* __restrict__ mask,
    h16* __restrict__ outh, float* __restrict__ outf) {
    extern __shared__ char smem[];
    uint32_t sb = smem_u32(smem);
    int tid = threadIdx.x, lid = tid & 31, wid = tid >> 5;
    int wm = wid >> 2, wn = wid & 3;   // 4x4 warp grid, warp tile 64x32

    // GROUP_M=8 rasterization (tiles: M 16, N 64)
    const int NTN = VV / GBN;          // 64
    int pid = blockIdx.x;
    int npg = 8 * NTN;                 // 512
    int gid = pid / npg;
    int pm = gid * 8 + (pid % 8);
    int pn = (pid % npg) / 8;
    int bm = pm * GBM, bn = pn * GBN;

    int lrow = tid >> 2, lch = tid & 3;   // 128 rows x 4 chunks per 512 threads
    const h16* gA = A + (size_t)bm * K;
    const h16* gB = B + (size_t)bn * K;

    uint32_t aoff = (uint32_t)((wm * 64 + (lid & 15)) * RSB + (lid >> 4) * 16);
    uint32_t boff = (uint32_t)((wn * 32 + (lid & 7) + ((lid >> 4) << 3)) * RSB + ((lid >> 3) & 1) * 16);

    float acc[4][4][4];
#pragma unroll
    for (int i = 0; i < 4; ++i)
#pragma unroll
        for (int j = 0; j < 4; ++j)
#pragma unroll
            for (int q = 0; q < 4; ++q) acc[i][j][q] = 0.0f;

    int nk = K / BKH;

    auto load = [&](int s) {
        uint32_t base = sb + (uint32_t)(s & 3) * STAGE;
        int k0 = s * BKH;
        // A: 256 rows in 2 iterations of 128
#pragma unroll
        for (int it = 0; it < 2; ++it) {
            int row = lrow + it * 128;
            uint32_t so = (uint32_t)(row * RSB + lch * 16);
            cp16(base + so, gA + (size_t)row * K + k0 + lch * 8);
        }
        // B: 128 rows in 1 iteration
        {
            uint32_t so = (uint32_t)(lrow * RSB + lch * 16);
            cp16(base + A_BYTES + so, gB + (size_t)lrow * K + k0 + lch * 8);
        }
    };

#pragma unroll
    for (int i = 0; i < 3; ++i) {
        if (i < nk) load(i);
        asm volatile("cp.async.commit_group;" ::: "memory");
    }

    for (int s = 0; s < nk; ++s) {
        asm volatile("cp.async.wait_group 2;" ::: "memory");
        __syncthreads();
        uint32_t base = sb + (uint32_t)(s & 3) * STAGE;
        uint32_t Ab = base + aoff;
        uint32_t Bb = base + A_BYTES + boff;
#pragma unroll
        for (int tk = 0; tk < 2; ++tk) {
            uint32_t a[4][4], bfr[4][2];
#pragma unroll
            for (int mi = 0; mi < 4; ++mi)
                ldsm4(a[mi][0], a[mi][1], a[mi][2], a[mi][3], Ab + mi * (16 * RSB) + tk * 32);
#pragma unroll
            for (int p = 0; p < 2; ++p) {
                uint32_t t0, t1, t2, t3;
                ldsm4(t0, t1, t2, t3, Bb + p * (16 * RSB) + tk * 32);
                bfr[p * 2][0] = t0;     bfr[p * 2][1] = t1;
                bfr[p * 2 + 1][0] = t2; bfr[p * 2 + 1][1] = t3;
            }
#pragma unroll
            for (int mi = 0; mi < 4; ++mi)
#pragma unroll
                for (int nj = 0; nj < 4; ++nj) mma16816(acc[mi][nj], a[mi], bfr[nj]);
        }
        if (s + 3 < nk) load(s + 3);
        asm volatile("cp.async.commit_group;" ::: "memory");
    }

    // epilogue
#pragma unroll
    for (int mi = 0; mi < 4; ++mi) {
        int rbase = bm + wm * 64 + mi * 16 + (lid >> 2);
#pragma unroll
        for (int nj = 0; nj < 4; ++nj) {
            int cn = bn + wn * 32 + nj * 8 + (lid & 3) * 2;
            float2 bv = *(const float2*)&bias[cn];
#pragma unroll
            for (int hh = 0; hh < 2; ++hh) {
                int row = rbase + hh * 8;
                size_t o = (size_t)row * VV + cn;
                float v0 = acc[mi][nj][hh * 2 + 0] + bv.x;
                float v1 = acc[mi][nj][hh * 2 + 1] + bv.y;
                if (EPI == 0) {
                    float2 mk = *(const float2*)&mask[o];
                    v0 = fmaxf(v0, 0.0f) * mk.x;
                    v1 = fmaxf(v1, 0.0f) * mk.y;
                    *(__half2*)(outh + o) = __floats2half2_rn(v0, v1);
                } else {
                    float2 rr;
                    rr.x = sigf(v0); rr.y = sigf(v1);
                    *(float2*)(outf + o) = rr;
                }
            }
        }
    }
}

// ---------------- launch ----------------
extern "C" void kernel_launch(void* const* d_in, const int* in_sizes, int n_in,
                              void* d_out, int out_size) {
    const int*   inp      = (const int*)  d_in[0];
    const float* E        = (const float*)d_in[1];
    const float* Wx       = (const float*)d_in[2];
    const float* U        = (const float*)d_in[3];
    const float* bb       = (const float*)d_in[4];
    const float* W1       = (const float*)d_in[5];
    const float* b1       = (const float*)d_in[6];
    const float* W1b      = (const float*)d_in[7];
    const float* W2       = (const float*)d_in[8];
    const float* b2       = (const float*)d_in[9];
    const float* rec_mask = (const float*)d_in[10];
    const float* dmask1   = (const float*)d_in[11];
    const float* dmask2   = (const float*)d_in[12];
    float* out = (float*)d_out;

    void *p_pooled, *p_w1t, *p_wbt, *p_w2t, *p_x1, *p_x2;
    cudaGetSymbolAddress(&p_pooled, g_pooled);
    cudaGetSymbolAddress(&p_w1t, g_W1t);
    cudaGetSymbolAddress(&p_wbt, g_W1bt);
    cudaGetSymbolAddress(&p_w2t, g_W2t);
    cudaGetSymbolAddress(&p_x1, g_x1);
    cudaGetSymbolAddress(&p_x2, g_x2);

    cudaFuncSetAttribute(hgemm<0>, cudaFuncAttributeMaxDynamicSharedMemorySize, GSMEM);
    cudaFuncSetAttribute(hgemm<1>, cudaFuncAttributeMaxDynamicSharedMemorySize, GSMEM);

    // Side stream for convT(W2) only; forked AFTER the latency-bound lstm is done
    // (r11 lesson: streaming kernels must not overlap the scan). Non-blocking to
    // avoid legacy-stream implicit serialization. Handles are host-side only.
    cudaStream_t s1;
    cudaStreamCreateWithFlags(&s1, cudaStreamNonBlocking);
    cudaEvent_t eFork, eW2;
    cudaEventCreateWithFlags(&eFork, cudaEventDisableTiming);
    cudaEventCreateWithFlags(&eW2, cudaEventDisableTiming);

    // main chain (serial, r6 ordering)
    w1t_kernel<<<(VV * 64) / 256, 256>>>(W1);
    ewx_kernel<<<VV, 256>>>(E, Wx, bb);
    lstm_kernel<<<BB, 256>>>(inp, U, rec_mask);
    convT_kernel<<<dim3(128, 128), dim3(16, 16)>>>(W1b, (h16*)p_wbt);

    // fork: convT(W2) overlaps GEMM1/GEMM2 (compute-bound; bandwidth headroom)
    cudaEventRecord(eFork, 0);
    cudaStreamWaitEvent(s1, eFork, 0);
    convT_kernel<<<dim3(128, 128), dim3(16, 16), 0, s1>>>(W2, (h16*)p_w2t);
    cudaEventRecord(eW2, s1);

    const int grid = (MM / GBM) * (VV / GBN);   // 16 * 64 = 1024
    // GEMM1  x1 = relu(pooled @ W1 + b1) * dmask1   (K = 64)
    hgemm<0><<<grid, 512, GSMEM>>>((const h16*)p_pooled, (const h16*)p_w1t, 64,
                                   b1, dmask1, (h16*)p_x1, nullptr);
    // GEMM2  x2 = relu(x1 @ W1b + b1) * dmask2      (K = 8192)
    hgemm<0><<<grid, 512, GSMEM>>>((const h16*)p_x1, (const h16*)p_wbt, VV,
                                   b1, dmask2, (h16*)p_x2, nullptr);
    // GEMM3  out = sigmoid(x2 @ W2 + b2)            (K = 8192)
    cudaStreamWaitEvent(0, eW2, 0);
    hgemm<1><<<grid, 512, GSMEM>>>((const h16*)p_x2, (const h16*)p_w2t, VV,
                                   b2, nullptr, nullptr, out);
}

// round 13
// speedup vs baseline: 1.5278x; 1.5278x over previous
#include <cuda_runtime.h>
#include <cuda_fp16.h>
#include <math.h>
#include <stdint.h>

#define BB   64
#define TT   128
#define HH   50
#define VV   8192
#define G4H  200
#define PP   64
#define MM   4096

typedef __half h16;

// ---------------- helpers ----------------
__device__ __forceinline__ uint32_t smem_u32(const void* p) {
    uint32_t a;
    asm("{ .reg .u64 t; cvta.to.shared.u64 t, %1; cvt.u32.u64 %0, t; }" : "=r"(a) : "l"(p));
    return a;
}
__device__ __forceinline__ void cp16(uint32_t saddr, const void* gptr) {
    asm volatile("cp.async.cg.shared.global [%0], [%1], 16;" :: "r"(saddr), "l"(gptr));
}
__device__ __forceinline__ void ldsm4(uint32_t& r0, uint32_t& r1, uint32_t& r2, uint32_t& r3, uint32_t addr) {
    asm volatile("ldmatrix.sync.aligned.m8n8.x4.shared.b16 {%0,%1,%2,%3}, [%4];"
                 : "=r"(r0), "=r"(r1), "=r"(r2), "=r"(r3) : "r"(addr));
}
__device__ __forceinline__ void mma16816(float* c, const uint32_t* a, const uint32_t* b) {
    asm volatile("mma.sync.aligned.m16n8k16.row.col.f32.f16.f16.f32 "
                 "{%0,%1,%2,%3}, {%4,%5,%6,%7}, {%8,%9}, {%0,%1,%2,%3};"
                 : "+f"(c[0]), "+f"(c[1]), "+f"(c[2]), "+f"(c[3])
                 : "r"(a[0]), "r"(a[1]), "r"(a[2]), "r"(a[3]), "r"(b[0]), "r"(b[1]));
}
__device__ __forceinline__ float sigf(float x) { return 1.0f / (1.0f + expf(-x)); }

// ---------------- scratch globals ----------------
__device__ __align__(256) float g_Ewx[VV * G4H];
__device__ __align__(256) h16 g_pooled[MM * 64];
__device__ __align__(256) h16 g_W1t[VV * 64];
__device__ __align__(256) h16 g_W1bt[(size_t)VV * VV];
__device__ __align__(256) h16 g_W2t[(size_t)VV * VV];
__device__ __align__(256) h16 g_x1[(size_t)MM * VV];
__device__ __align__(256) h16 g_x2[(size_t)MM * VV];

// ---------------- fused prep kernel (round-6 proven) ----------------
__device__ __forceinline__ void convT_body(const float* __restrict__ W, h16* __restrict__ Wt,
                                           int bid, int tid, float (*t)[33]) {
    int tx = tid & 15, ty = tid >> 4;
    int bx = bid & 255, by = bid >> 8;
    int col = bx * 32 + 2 * tx;
#pragma unroll
    for (int i = 0; i < 32; i += 16) {
        int row = by * 32 + ty + i;
        float2 v = *(const float2*)&W[(size_t)row * VV + col];
        t[ty + i][2 * tx]     = v.x;
        t[ty + i][2 * tx + 1] = v.y;
    }
    __syncthreads();
#pragma unroll
    for (int i = 0; i < 32; i += 16) {
        int n = bx * 32 + ty + i;
        int k = by * 32 + 2 * tx;
        __half2 h = __floats2half2_rn(t[2 * tx][ty + i], t[2 * tx + 1][ty + i]);
        *(__half2*)(Wt + (size_t)n * VV + k) = h;
    }
}

__global__ void prep_kernel(const float* __restrict__ E, const float* __restrict__ Wx,
                            const float* __restrict__ bias, const float* __restrict__ W1,
                            const float* __restrict__ W1b, const float* __restrict__ W2) {
    __shared__ float t[32][33];
    int b = blockIdx.x, tid = threadIdx.x;
    if (b < VV) {
        if (tid < HH) t[0][tid] = E[b * HH + tid];
        __syncthreads();
        if (tid < G4H) {
            float acc = bias[tid];
            const float* e = &t[0][0];
#pragma unroll
            for (int h = 0; h < HH; ++h) acc = fmaf(e[h], Wx[h * G4H + tid], acc);
            g_Ewx[(size_t)b * G4H + tid] = acc;
        }
    } else if (b < VV + 2048) {
        int i = (b - VV) * 256 + tid;   // n*64 + k
        int n = i >> 6, k = i & 63;
        float v = (k < HH) ? W1[(size_t)k * VV + n] : 0.0f;
        g_W1t[i] = __float2half_rn(v);
    } else if (b < VV + 2048 + 65536) {
        convT_body(W1b, g_W1bt, b - (VV + 2048), tid, t);
    } else {
        convT_body(W2, g_W2t, b - (VV + 2048 + 65536), tid, t);
    }
}

// ---------------- LSTM scan + fused MaxPool(2), fp16 out ----------------
// vs r6: z-input rows double-buffered in SMEM via cp.async (prefetch t+1 during step t),
// indices preloaded once. Removes the per-step serial gather latency.
__global__ void lstm_kernel(const int* __restrict__ inp, const float* __restrict__ U,
                            const float* __restrict__ rec_mask) {
    __shared__ float sU[4 * HH * HH];
    __shared__ float rm[G4H], hm[G4H], z[G4H];
    __shared__ __align__(16) float zbuf[2][G4H];
    __shared__ float h[HH], c[HH], hprev[HH];
    __shared__ int sidx[TT];
    int b = blockIdx.x, tid = threadIdx.x;

    for (int i = tid; i < 4 * HH * HH; i += 256) sU[i] = U[i];
    if (tid < TT) sidx[tid] = inp[b * TT + tid];
    if (tid < G4H) {
        int g = tid / HH, j = tid - g * HH;
        rm[tid] = rec_mask[((size_t)g * BB + b) * HH + j];
    }
    if (tid < HH) { h[tid] = 0.0f; c[tid] = 0.0f; hprev[tid] = 0.0f; }
    __syncthreads();

    uint32_t zb[2];
    zb[0] = smem_u32(&zbuf[0][0]);
    zb[1] = smem_u32(&zbuf[1][0]);

    // prefetch step 0 (800 B = 50 x 16 B)
    if (tid < 50) cp16(zb[0] + tid * 16, g_Ewx + (size_t)sidx[0] * G4H + tid * 4);
    asm volatile("cp.async.commit_group;" ::: "memory");

    for (int t = 0; t < TT; ++t) {
        // prefetch t+1 into the other buffer (its readers finished at t-1's trailing sync)
        if (t + 1 < TT && tid < 50)
            cp16(zb[(t + 1) & 1] + tid * 16, g_Ewx + (size_t)sidx[t + 1] * G4H + tid * 4);
        asm volatile("cp.async.commit_group;" ::: "memory");
        asm volatile("cp.async.wait_group 1;" ::: "memory");

        if (tid < G4H) hm[tid] = h[tid % HH] * rm[tid];
        __syncthreads();   // zbuf[t&1] + hm visible to all
        if (tid < G4H) {
            int g = tid / HH, j = tid - g * HH;
            float acc = zbuf[t & 1][tid];
            const float* Ug = sU + g * HH * HH + j;
            const float* hg = hm + g * HH;
#pragma unroll
            for (int k = 0; k < HH; ++k) acc = fmaf(hg[k], Ug[k * HH], acc);
            z[tid] = acc;
        }
        __syncthreads();
        if (tid < HH) {
            float iv = sigf(z[tid]);
            float fv = sigf(z[HH + tid]);
            float gv = tanhf(z[2 * HH + tid]);
            float ov = sigf(z[3 * HH + tid]);
            float cn = fv * c[tid] + iv * gv;
            float hn = ov * tanhf(cn);
            c[tid] = cn;
            h[tid] = hn;
            if (t & 1) {
                g_pooled[((size_t)b * PP + (t >> 1)) * 64 + tid] = __float2half_rn(fmaxf(hprev[tid], hn));
            } else hprev[tid] = hn;
        } else if (tid < 64 && (t & 1)) {
            g_pooled[((size_t)b * PP + (t >> 1)) * 64 + tid] = __float2half_rn(0.0f);
        }
        __syncthreads();
    }
}

// ---------------- fp16 HMMA GEMM (round-6 proven config, byte-identical) ----------------
#define GBM 256
#define GBN 128
#define BKH 32
#define RSB 80                        // 64B data + 16B pad
#define A_BYTES (GBM * RSB)           // 20480
#define STAGE ((GBM + GBN) * RSB)     // 30720
#define GSMEM (4 * STAGE)             // 122880

template <int EPI>
__global__ void __launch_bounds__(512) hgemm(
    const h16* __restrict__ A, const h16* __restrict__ B, int K,
    const float* __restrict__ bias, const float* __restrict__ mask,
    h16* __restrict__ outh, float* __restrict__ outf) {
    extern __shared__ char smem[];
    uint32_t sb = smem_u32(smem);
    int tid = threadIdx.x, lid = tid & 31, wid = tid >> 5;
    int wm = wid >> 2, wn = wid & 3;   // 4x4 warp grid, warp tile 64x32

    const int NTN = VV / GBN;          // 64
    int pid = blockIdx.x;
    int npg = 8 * NTN;                 // 512
    int gid = pid / npg;
    int pm = gid * 8 + (pid % 8);
    int pn = (pid % npg) / 8;
    int bm = pm * GBM, bn = pn * GBN;

    int lrow = tid >> 2, lch = tid & 3;
    const h16* gA = A + (size_t)bm * K;
    const h16* gB = B + (size_t)bn * K;

    uint32_t aoff = (uint32_t)((wm * 64 + (lid & 15)) * RSB + (lid >> 4) * 16);
    uint32_t boff = (uint32_t)((wn * 32 + (lid & 7) + ((lid >> 4) << 3)) * RSB + ((lid >> 3) & 1) * 16);

    float acc[4][4][4];
#pragma unroll
    for (int i = 0; i < 4; ++i)
#pragma unroll
        for (int j = 0; j < 4; ++j)
#pragma unroll
            for (int q = 0; q < 4; ++q) acc[i][j][q] = 0.0f;

    int nk = K / BKH;

    auto load = [&](int s) {
        uint32_t base = sb + (uint32_t)(s & 3) * STAGE;
        int k0 = s * BKH;
#pragma unroll
        for (int it = 0; it < 2; ++it) {
            int row = lrow + it * 128;
            uint32_t so = (uint32_t)(row * RSB + lch * 16);
            cp16(base + so, gA + (size_t)row * K + k0 + lch * 8);
        }
        {
            uint32_t so = (uint32_t)(lrow * RSB + lch * 16);
            cp16(base + A_BYTES + so, gB + (size_t)lrow * K + k0 + lch * 8);
        }
    };

#pragma unroll
    for (int i = 0; i < 3; ++i) {
        if (i < nk) load(i);
        asm volatile("cp.async.commit_group;" ::: "memory");
    }

    for (int s = 0; s < nk; ++s) {
        asm volatile("cp.async.wait_group 2;" ::: "memory");
        __syncthreads();
        uint32_t base = sb + (uint32_t)(s & 3) * STAGE;
        uint32_t Ab = base + aoff;
        uint32_t Bb = base + A_BYTES + boff;
#pragma unroll
        for (int tk = 0; tk < 2; ++tk) {
            uint32_t a[4][4], bfr[4][2];
#pragma unroll
            for (int mi = 0; mi < 4; ++mi)
                ldsm4(a[mi][0], a[mi][1], a[mi][2], a[mi][3], Ab + mi * (16 * RSB) + tk * 32);
#pragma unroll
            for (int p = 0; p < 2; ++p) {
                uint32_t t0, t1, t2, t3;
                ldsm4(t0, t1, t2, t3, Bb + p * (16 * RSB) + tk * 32);
                bfr[p * 2][0] = t0;     bfr[p * 2][1] = t1;
                bfr[p * 2 + 1][0] = t2; bfr[p * 2 + 1][1] = t3;
            }
#pragma unroll
            for (int mi = 0; mi < 4; ++mi)
#pragma unroll
                for (int nj = 0; nj < 4; ++nj) mma16816(acc[mi][nj], a[mi], bfr[nj]);
        }
        if (s + 3 < nk) load(s + 3);
        asm volatile("cp.async.commit_group;" ::: "memory");
    }

#pragma unroll
    for (int mi = 0; mi < 4; ++mi) {
        int rbase = bm + wm * 64 + mi * 16 + (lid >> 2);
#pragma unroll
        for (int nj = 0; nj < 4; ++nj) {
            int cn = bn + wn * 32 + nj * 8 + (lid & 3) * 2;
            float2 bv = *(const float2*)&bias[cn];
#pragma unroll
            for (int hh = 0; hh < 2; ++hh) {
                int row = rbase + hh * 8;
                size_t o = (size_t)row * VV + cn;
                float v0 = acc[mi][nj][hh * 2 + 0] + bv.x;
                float v1 = acc[mi][nj][hh * 2 + 1] + bv.y;
                if (EPI == 0) {
                    float2 mk = *(const float2*)&mask[o];
                    v0 = fmaxf(v0, 0.0f) * mk.x;
                    v1 = fmaxf(v1, 0.0f) * mk.y;
                    *(__half2*)(outh + o) = __floats2half2_rn(v0, v1);
                } else {
                    float2 rr;
                    rr.x = sigf(v0); rr.y = sigf(v1);
                    *(float2*)(outf + o) = rr;
                }
            }
        }
    }
}

// ---------------- launch (round-6 serial ordering) ----------------
extern "C" void kernel_launch(void* const* d_in, const int* in_sizes, int n_in,
                              void* d_out, int out_size) {
    const int*   inp      = (const int*)  d_in[0];
    const float* E        = (const float*)d_in[1];
    const float* Wx       = (const float*)d_in[2];
    const float* U        = (const float*)d_in[3];
    const float* bb       = (const float*)d_in[4];
    const float* W1       = (const float*)d_in[5];
    const float* b1       = (const float*)d_in[6];
    const float* W1b      = (const float*)d_in[7];
    const float* W2       = (const float*)d_in[8];
    const float* b2       = (const float*)d_in[9];
    const float* rec_mask = (const float*)d_in[10];
    const float* dmask1   = (const float*)d_in[11];
    const float* dmask2   = (const float*)d_in[12];
    float* out = (float*)d_out;

    void *p_pooled, *p_w1t, *p_wbt, *p_w2t, *p_x1, *p_x2;
    cudaGetSymbolAddress(&p_pooled, g_pooled);
    cudaGetSymbolAddress(&p_w1t, g_W1t);
    cudaGetSymbolAddress(&p_wbt, g_W1bt);
    cudaGetSymbolAddress(&p_w2t, g_W2t);
    cudaGetSymbolAddress(&p_x1, g_x1);
    cudaGetSymbolAddress(&p_x2, g_x2);

    cudaFuncSetAttribute(hgemm<0>, cudaFuncAttributeMaxDynamicSharedMemorySize, GSMEM);
    cudaFuncSetAttribute(hgemm<1>, cudaFuncAttributeMaxDynamicSharedMemorySize, GSMEM);

    prep_kernel<<<VV + 2048 + 2 * 65536, 256>>>(E, Wx, bb, W1, W1b, W2);
    lstm_kernel<<<BB, 256>>>(inp, U, rec_mask);

    const int grid = (MM / GBM) * (VV / GBN);   // 16 * 64 = 1024
    hgemm<0><<<grid, 512, GSMEM>>>((const h16*)p_pooled, (const h16*)p_w1t, 64,
                                   b1, dmask1, (h16*)p_x1, nullptr);
    hgemm<0><<<grid, 512, GSMEM>>>((const h16*)p_x1, (const h16*)p_wbt, VV,
                                   b1, dmask2, (h16*)p_x2, nullptr);
    hgemm<1><<<grid, 512, GSMEM>>>((const h16*)p_x2, (const h16*)p_w2t, VV,
                                   b2, nullptr, nullptr, out);
}

// round 14
// speedup vs baseline: 1.6154x; 1.0574x over previous
#include <cuda_runtime.h>
#include <cuda_fp16.h>
#include <math.h>
#include <stdint.h>

#define BB   64
#define TT   128
#define HH   50
#define VV   8192
#define G4H  200
#define PP   64
#define MM   4096

typedef __half h16;

// ---------------- helpers ----------------
__device__ __forceinline__ uint32_t smem_u32(const void* p) {
    uint32_t a;
    asm("{ .reg .u64 t; cvta.to.shared.u64 t, %1; cvt.u32.u64 %0, t; }" : "=r"(a) : "l"(p));
    return a;
}
__device__ __forceinline__ void cp16(uint32_t saddr, const void* gptr) {
    asm volatile("cp.async.cg.shared.global [%0], [%1], 16;" :: "r"(saddr), "l"(gptr));
}
__device__ __forceinline__ void ldsm4(uint32_t& r0, uint32_t& r1, uint32_t& r2, uint32_t& r3, uint32_t addr) {
    asm volatile("ldmatrix.sync.aligned.m8n8.x4.shared.b16 {%0,%1,%2,%3}, [%4];"
                 : "=r"(r0), "=r"(r1), "=r"(r2), "=r"(r3) : "r"(addr));
}
__device__ __forceinline__ void ldsm4t(uint32_t& r0, uint32_t& r1, uint32_t& r2, uint32_t& r3, uint32_t addr) {
    asm volatile("ldmatrix.sync.aligned.m8n8.x4.trans.shared.b16 {%0,%1,%2,%3}, [%4];"
                 : "=r"(r0), "=r"(r1), "=r"(r2), "=r"(r3) : "r"(addr));
}
__device__ __forceinline__ void mma16816(float* c, const uint32_t* a, const uint32_t* b) {
    asm volatile("mma.sync.aligned.m16n8k16.row.col.f32.f16.f16.f32 "
                 "{%0,%1,%2,%3}, {%4,%5,%6,%7}, {%8,%9}, {%0,%1,%2,%3};"
                 : "+f"(c[0]), "+f"(c[1]), "+f"(c[2]), "+f"(c[3])
                 : "r"(a[0]), "r"(a[1]), "r"(a[2]), "r"(a[3]), "r"(b[0]), "r"(b[1]));
}
__device__ __forceinline__ float sigf(float x) { return 1.0f / (1.0f + expf(-x)); }

// ---------------- scratch globals ----------------
__device__ __align__(256) float g_Ewx[VV * G4H];
__device__ __align__(256) h16 g_pooled[MM * 64];
__device__ __align__(256) h16 g_W1p[64 * VV];                 // W1 zero-padded [64][V] fp16 (native K-major)
__device__ __align__(256) h16 g_W1bh[(size_t)VV * VV];        // W1b fp16, native [K][N]
__device__ __align__(256) h16 g_W2h[(size_t)VV * VV];         // W2  fp16, native [K][N]
__device__ __align__(256) h16 g_x1[(size_t)MM * VV];
__device__ __align__(256) h16 g_x2[(size_t)MM * VV];

// ---------------- fused prep kernel ----------------
// blocks [0, 8192):              ewx: Ewx = E@Wx + b
// blocks [8192, 8448):           W1 [50,V] -> [64,V] fp16 (straight copy + zero pad)
// blocks [8448, 8448+32768):     W1b fp32 -> fp16 streaming convert (no transpose)
// blocks [.., +32768):           W2  fp32 -> fp16 streaming convert
#define NB_EWX  VV
#define NB_W1   ((64 * VV) / 2048)                 // 256
#define NB_CONV (((size_t)VV * VV) / 2048)         // 32768

__device__ __forceinline__ void convS_body(const float* __restrict__ W, h16* __restrict__ Wh,
                                           size_t i) {
    float4 a = *(const float4*)&W[i];
    float4 b = *(const float4*)&W[i + 4];
    __half2 h0 = __floats2half2_rn(a.x, a.y);
    __half2 h1 = __floats2half2_rn(a.z, a.w);
    __half2 h2 = __floats2half2_rn(b.x, b.y);
    __half2 h3 = __floats2half2_rn(b.z, b.w);
    uint4 pk;
    pk.x = *(uint32_t*)&h0; pk.y = *(uint32_t*)&h1;
    pk.z = *(uint32_t*)&h2; pk.w = *(uint32_t*)&h3;
    *(uint4*)&Wh[i] = pk;
}

__global__ void prep_kernel(const float* __restrict__ E, const float* __restrict__ Wx,
                            const float* __restrict__ bias, const float* __restrict__ W1,
                            const float* __restrict__ W1b, const float* __restrict__ W2) {
    __shared__ float e[HH];
    int b = blockIdx.x, tid = threadIdx.x;
    if (b < NB_EWX) {
        if (tid < HH) e[tid] = E[b * HH + tid];
        __syncthreads();
        if (tid < G4H) {
            float acc = bias[tid];
#pragma unroll
            for (int h = 0; h < HH; ++h) acc = fmaf(e[h], Wx[h * G4H + tid], acc);
            g_Ewx[(size_t)b * G4H + tid] = acc;
        }
    } else if (b < NB_EWX + NB_W1) {
        size_t i = (size_t)(b - NB_EWX) * 2048 + (size_t)tid * 8;
        if (i < (size_t)HH * VV) {
            convS_body(W1, g_W1p, i);
        } else {
            uint4 z = {0, 0, 0, 0};
            *(uint4*)&g_W1p[i] = z;
        }
    } else if (b < NB_EWX + NB_W1 + (int)NB_CONV) {
        size_t i = (size_t)(b - NB_EWX - NB_W1) * 2048 + (size_t)tid * 8;
        convS_body(W1b, g_W1bh, i);
    } else {
        size_t i = (size_t)(b - NB_EWX - NB_W1 - (int)NB_CONV) * 2048 + (size_t)tid * 8;
        convS_body(W2, g_W2h, i);
    }
}

// ---------------- LSTM scan + fused MaxPool(2), fp16 out (r13 proven) ----------------
__global__ void lstm_kernel(const int* __restrict__ inp, const float* __restrict__ U,
                            const float* __restrict__ rec_mask) {
    __shared__ float sU[4 * HH * HH];
    __shared__ float rm[G4H], hm[G4H], z[G4H];
    __shared__ __align__(16) float zbuf[2][G4H];
    __shared__ float h[HH], c[HH], hprev[HH];
    __shared__ int sidx[TT];
    int b = blockIdx.x, tid = threadIdx.x;

    for (int i = tid; i < 4 * HH * HH; i += 256) sU[i] = U[i];
    if (tid < TT) sidx[tid] = inp[b * TT + tid];
    if (tid < G4H) {
        int g = tid / HH, j = tid - g * HH;
        rm[tid] = rec_mask[((size_t)g * BB + b) * HH + j];
    }
    if (tid < HH) { h[tid] = 0.0f; c[tid] = 0.0f; hprev[tid] = 0.0f; }
    __syncthreads();

    uint32_t zb[2];
    zb[0] = smem_u32(&zbuf[0][0]);
    zb[1] = smem_u32(&zbuf[1][0]);

    if (tid < 50) cp16(zb[0] + tid * 16, g_Ewx + (size_t)sidx[0] * G4H + tid * 4);
    asm volatile("cp.async.commit_group;" ::: "memory");

    for (int t = 0; t < TT; ++t) {
        if (t + 1 < TT && tid < 50)
            cp16(zb[(t + 1) & 1] + tid * 16, g_Ewx + (size_t)sidx[t + 1] * G4H + tid * 4);
        asm volatile("cp.async.commit_group;" ::: "memory");
        asm volatile("cp.async.wait_group 1;" ::: "memory");

        if (tid < G4H) hm[tid] = h[tid % HH] * rm[tid];
        __syncthreads();
        if (tid < G4H) {
            int g = tid / HH, j = tid - g * HH;
            float acc = zbuf[t & 1][tid];
            const float* Ug = sU + g * HH * HH + j;
            const float* hg = hm + g * HH;
#pragma unroll
            for (int k = 0; k < HH; ++k) acc = fmaf(hg[k], Ug[k * HH], acc);
            z[tid] = acc;
        }
        __syncthreads();
        if (tid < HH) {
            float iv = sigf(z[tid]);
            float fv = sigf(z[HH + tid]);
            float gv = tanhf(z[2 * HH + tid]);
            float ov = sigf(z[3 * HH + tid]);
            float cn = fv * c[tid] + iv * gv;
            float hn = ov * tanhf(cn);
            c[tid] = cn;
            h[tid] = hn;
            if (t & 1) {
                g_pooled[((size_t)b * PP + (t >> 1)) * 64 + tid] = __float2half_rn(fmaxf(hprev[tid], hn));
            } else hprev[tid] = hn;
        } else if (tid < 64 && (t & 1)) {
            g_pooled[((size_t)b * PP + (t >> 1)) * 64 + tid] = __float2half_rn(0.0f);
        }
        __syncthreads();
    }
}

// ---------------- fp16 HMMA GEMM, CTA 256x128xBK32, 512 threads, 4-stage ring ----------------
// B is ROW-MAJOR [K][N] fp16 (ld = VV); loaded into smem [32 k-rows][256B] and consumed via
// ldmatrix.x4.trans. A-side, schedule, epilogues identical to the r6/r13 proven config.
// C[M=4096, N=8192] = epi(A[M,K] @ B[K,N] + bias)
// EPI 0: relu(+bias)*mask -> fp16.  EPI 1: sigmoid(+bias) -> fp32.
#define GBM 256
#define GBN 128
#define BKH 32
#define RSA 80                        // A row stride: 64B data + 16B pad
#define RSBB 272                      // B row stride: 256B data + 16B pad (conflict-free trans)
#define A_BYTES (GBM * RSA)           // 20480
#define B_BYTES (BKH * RSBB)          // 8704
#define STAGE (A_BYTES + B_BYTES)     // 29184
#define GSMEM (4 * STAGE)             // 116736

template <int EPI>
__global__ void __launch_bounds__(512) hgemm(
    const h16* __restrict__ A, const h16* __restrict__ B, int K,
    const float* __restrict__ bias, const float* __restrict__ mask,
    h16* __restrict__ outh, float* __restrict__ outf) {
    extern __shared__ char smem[];
    uint32_t sb = smem_u32(smem);
    int tid = threadIdx.x, lid = tid & 31, wid = tid >> 5;
    int wm = wid >> 2, wn = wid & 3;   // 4x4 warp grid, warp tile 64x32

    // GROUP_M=8 rasterization (tiles: M 16, N 64)
    const int NTN = VV / GBN;          // 64
    int pid = blockIdx.x;
    int npg = 8 * NTN;                 // 512
    int gid = pid / npg;
    int pm = gid * 8 + (pid % 8);
    int pn = (pid % npg) / 8;
    int bm = pm * GBM, bn = pn * GBN;

    // A cp.async mapping: 128 rows x 4 chunks per 512 threads
    int lrowA = tid >> 2, lchA = tid & 3;
    // B cp.async mapping: 32 rows x 16 chunks (16B each = 256B row)
    int lrowB = tid >> 4, lchB = tid & 15;
    const h16* gA = A + (size_t)bm * K;
    const h16* gBn = B + bn;           // row-major [K][VV], column offset bn

    uint32_t aoff = (uint32_t)((wm * 64 + (lid & 15)) * RSA + (lid >> 4) * 16);
    // trans-B lane address: k-row = lid&15, n-col = wn*32 + (lid>>4)*8
    uint32_t boff = (uint32_t)((lid & 15) * RSBB + (wn * 32 + ((lid >> 4) << 3)) * 2);

    float acc[4][4][4];
#pragma unroll
    for (int i = 0; i < 4; ++i)
#pragma unroll
        for (int j = 0; j < 4; ++j)
#pragma unroll
            for (int q = 0; q < 4; ++q) acc[i][j][q] = 0.0f;

    int nk = K / BKH;

    auto load = [&](int s) {
        uint32_t base = sb + (uint32_t)(s & 3) * STAGE;
        int k0 = s * BKH;
        // A: 256 rows in 2 iterations of 128
#pragma unroll
        for (int it = 0; it < 2; ++it) {
            int row = lrowA + it * 128;
            uint32_t so = (uint32_t)(row * RSA + lchA * 16);
            cp16(base + so, gA + (size_t)row * K + k0 + lchA * 8);
        }
        // B: 32 k-rows x 256B in one shot
        {
            uint32_t so = (uint32_t)(lrowB * RSBB + lchB * 16);
            cp16(base + A_BYTES + so, gBn + (size_t)(k0 + lrowB) * VV + lchB * 8);
        }
    };

#pragma unroll
    for (int i = 0; i < 3; ++i) {
        if (i < nk) load(i);
        asm volatile("cp.async.commit_group;" ::: "memory");
    }

    for (int s = 0; s < nk; ++s) {
        asm volatile("cp.async.wait_group 2;" ::: "memory");
        __syncthreads();
        uint32_t base = sb + (uint32_t)(s & 3) * STAGE;
        uint32_t Ab = base + aoff;
        uint32_t Bb = base + A_BYTES + boff;
#pragma unroll
        for (int tk = 0; tk < 2; ++tk) {
            uint32_t a[4][4], bfr[4][2];
#pragma unroll
            for (int mi = 0; mi < 4; ++mi)
                ldsm4(a[mi][0], a[mi][1], a[mi][2], a[mi][3], Ab + mi * (16 * RSA) + tk * 32);
            // B fragments via trans: k-half = tk (16 rows), 2 calls cover n 0..15 / 16..31
            {
                uint32_t kbase = Bb + (uint32_t)tk * (16 * RSBB);
                uint32_t t0, t1, t2, t3;
                ldsm4t(t0, t1, t2, t3, kbase);
                bfr[0][0] = t0; bfr[0][1] = t1;
                bfr[1][0] = t2; bfr[1][1] = t3;
                ldsm4t(t0, t1, t2, t3, kbase + 32);
                bfr[2][0] = t0; bfr[2][1] = t1;
                bfr[3][0] = t2; bfr[3][1] = t3;
            }
#pragma unroll
            for (int mi = 0; mi < 4; ++mi)
#pragma unroll
                for (int nj = 0; nj < 4; ++nj) mma16816(acc[mi][nj], a[mi], bfr[nj]);
        }
        if (s + 3 < nk) load(s + 3);
        asm volatile("cp.async.commit_group;" ::: "memory");
    }

    // epilogue
#pragma unroll
    for (int mi = 0; mi < 4; ++mi) {
        int rbase = bm + wm * 64 + mi * 16 + (lid >> 2);
#pragma unroll
        for (int nj = 0; nj < 4; ++nj) {
            int cn = bn + wn * 32 + nj * 8 + (lid & 3) * 2;
            float2 bv = *(const float2*)&bias[cn];
#pragma unroll
            for (int hh = 0; hh < 2; ++hh) {
                int row = rbase + hh * 8;
                size_t o = (size_t)row * VV + cn;
                float v0 = acc[mi][nj][hh * 2 + 0] + bv.x;
                float v1 = acc[mi][nj][hh * 2 + 1] + bv.y;
                if (EPI == 0) {
                    float2 mk = *(const float2*)&mask[o];
                    v0 = fmaxf(v0, 0.0f) * mk.x;
                    v1 = fmaxf(v1, 0.0f) * mk.y;
                    *(__half2*)(outh + o) = __floats2half2_rn(v0, v1);
                } else {
                    float2 rr;
                    rr.x = sigf(v0); rr.y = sigf(v1);
                    *(float2*)(outf + o) = rr;
                }
            }
        }
    }
}

// ---------------- launch (serial, r6/r13 ordering) ----------------
extern "C" void kernel_launch(void* const* d_in, const int* in_sizes, int n_in,
                              void* d_out, int out_size) {
    const int*   inp      = (const int*)  d_in[0];
    const float* E        = (const float*)d_in[1];
    const float* Wx       = (const float*)d_in[2];
    const float* U        = (const float*)d_in[3];
    const float* bb       = (const float*)d_in[4];
    const float* W1       = (const float*)d_in[5];
    const float* b1       = (const float*)d_in[6];
    const float* W1b      = (const float*)d_in[7];
    const float* W2       = (const float*)d_in[8];
    const float* b2       = (const float*)d_in[9];
    const float* rec_mask = (const float*)d_in[10];
    const float* dmask1   = (const float*)d_in[11];
    const float* dmask2   = (const float*)d_in[12];
    float* out = (float*)d_out;

    void *p_pooled, *p_w1p, *p_wbh, *p_w2h, *p_x1, *p_x2;
    cudaGetSymbolAddress(&p_pooled, g_pooled);
    cudaGetSymbolAddress(&p_w1p, g_W1p);
    cudaGetSymbolAddress(&p_wbh, g_W1bh);
    cudaGetSymbolAddress(&p_w2h, g_W2h);
    cudaGetSymbolAddress(&p_x1, g_x1);
    cudaGetSymbolAddress(&p_x2, g_x2);

    cudaFuncSetAttribute(hgemm<0>, cudaFuncAttributeMaxDynamicSharedMemorySize, GSMEM);
    cudaFuncSetAttribute(hgemm<1>, cudaFuncAttributeMaxDynamicSharedMemorySize, GSMEM);

    // launch 0: all preprocessing fused (no transposes — pure streaming converts)
    prep_kernel<<<NB_EWX + NB_W1 + 2 * (int)NB_CONV, 256>>>(E, Wx, bb, W1, W1b, W2);
    // launch 1: lstm (z-row prefetch version)
    lstm_kernel<<<BB, 256>>>(inp, U, rec_mask);

    const int grid = (MM / GBM) * (VV / GBN);   // 16 * 64 = 1024
    // launch 2: GEMM1  x1 = relu(pooled @ W1 + b1) * dmask1   (K = 64, B = [64][V])
    hgemm<0><<<grid, 512, GSMEM>>>((const h16*)p_pooled, (const h16*)p_w1p, 64,
                                   b1, dmask1, (h16*)p_x1, nullptr);
    // launch 3: GEMM2  x2 = relu(x1 @ W1b + b1) * dmask2      (K = 8192)
    hgemm<0><<<grid, 512, GSMEM>>>((const h16*)p_x1, (const h16*)p_wbh, VV,
                                   b1, dmask2, (h16*)p_x2, nullptr);
    // launch 4: GEMM3  out = sigmoid(x2 @ W2 + b2)            (K = 8192)
    hgemm<1><<<grid, 512, GSMEM>>>((const h16*)p_x2, (const h16*)p_w2h, VV,
                                   b2, nullptr, nullptr, out);
}